// round 2
// baseline (speedup 1.0000x reference)
#include <cuda_runtime.h>
#include <math.h>

// Problem constants
#define T_TOK 4096      // B*S
#define HDIM  1024
#define IDIM  2816
#define EDIM  8
#define TOPK  2
#define NPAIR (T_TOK*TOPK)   // 8192

// GEMM tiling
#define BM 128
#define BN 64
#define BK 8
#define TM 8
#define TN 4

// ---------------- scratch (__device__ globals: alloc-free) ----------------
__device__ int   g_cnt[EDIM];
__device__ int   g_off[EDIM + 1];
__device__ int   g_fill[EDIM];
__device__ int   g_tok_e[NPAIR];      // per token: top-2 expert ids
__device__ float g_tok_w[NPAIR];      // per token: top-2 weights
__device__ int   g_list[NPAIR];       // pair slot -> token index (grouped by expert)
__device__ float g_wt[NPAIR];         // pair slot -> weight
__device__ int   g_tokpair[NPAIR];    // token,k -> pair slot
__device__ float g_act[(size_t)NPAIR * IDIM];      // 92.3 MB
__device__ float g_pairout[(size_t)NPAIR * HDIM];  // 33.5 MB

// ---------------- kernels ----------------

__global__ void zero_kernel() {
    int i = threadIdx.x;
    if (i < EDIM) { g_cnt[i] = 0; }
}

// One block per token: logits (8), top-2, softmax weights, atomic counts.
__global__ void router_kernel(const float* __restrict__ x,
                              const float* __restrict__ gw,
                              float* __restrict__ out_logits) {
    const int t = blockIdx.x;
    const int tid = threadIdx.x;
    float acc[EDIM];
#pragma unroll
    for (int e = 0; e < EDIM; e++) acc[e] = 0.f;

    const float* xr = x + (size_t)t * HDIM;
    for (int h = tid; h < HDIM; h += 128) {
        float xv = xr[h];
        const float* gr = gw + (size_t)h * EDIM;
#pragma unroll
        for (int e = 0; e < EDIM; e++) acc[e] += xv * gr[e];
    }

    __shared__ float red[EDIM][128];
#pragma unroll
    for (int e = 0; e < EDIM; e++) red[e][tid] = acc[e];
    __syncthreads();
    for (int s = 64; s > 0; s >>= 1) {
        if (tid < s) {
#pragma unroll
            for (int e = 0; e < EDIM; e++) red[e][tid] += red[e][tid + s];
        }
        __syncthreads();
    }

    if (tid == 0) {
        float l[EDIM];
#pragma unroll
        for (int e = 0; e < EDIM; e++) {
            l[e] = red[e][0];
            out_logits[(size_t)t * EDIM + e] = l[e];
        }
        // top-2 (strict >, ties -> lowest index, matching jax top_k)
        int i0 = 0;
#pragma unroll
        for (int e = 1; e < EDIM; e++) if (l[e] > l[i0]) i0 = e;
        int i1 = -1;
#pragma unroll
        for (int e = 0; e < EDIM; e++) {
            if (e == i0) continue;
            if (i1 < 0 || l[e] > l[i1]) i1 = e;
        }
        float e1 = expf(l[i1] - l[i0]);
        float w0 = 1.f / (1.f + e1);
        float w1 = e1 / (1.f + e1);
        g_tok_e[t * 2 + 0] = i0; g_tok_w[t * 2 + 0] = w0;
        g_tok_e[t * 2 + 1] = i1; g_tok_w[t * 2 + 1] = w1;
        atomicAdd(&g_cnt[i0], 1);
        atomicAdd(&g_cnt[i1], 1);
    }
}

__global__ void scan_kernel() {
    int s = 0;
    for (int e = 0; e < EDIM; e++) {
        g_off[e] = s;
        s += g_cnt[e];
        g_fill[e] = 0;
    }
    g_off[EDIM] = s;
}

__global__ void assign_kernel() {
    int t = blockIdx.x * blockDim.x + threadIdx.x;
    if (t >= T_TOK) return;
#pragma unroll
    for (int k = 0; k < TOPK; k++) {
        int e = g_tok_e[t * 2 + k];
        int slot = atomicAdd(&g_fill[e], 1);
        int p = g_off[e] + slot;
        g_list[p] = t;
        g_wt[p] = g_tok_w[t * 2 + k];
        g_tokpair[t * 2 + k] = p;
    }
}

// Fused gate+up grouped GEMM with SwiGLU epilogue -> g_act
// grid: (IDIM/BN, 32, EDIM), 256 threads
__global__ __launch_bounds__(256, 2) void gateup_kernel(
    const float* __restrict__ x,
    const float* __restrict__ Wg,
    const float* __restrict__ Wu) {
    const int e = blockIdx.z;
    const int ne = g_cnt[e];
    const int m0 = blockIdx.y * BM;
    if (m0 >= ne) return;
    const int n0 = blockIdx.x * BN;
    const int off = g_off[e];

    __shared__ float As[BK][BM];
    __shared__ float Bg[BK][BN];
    __shared__ float Bu[BK][BN];
    __shared__ int rowtok[BM];

    const int tid = threadIdx.x;
    const int tx = tid & 15;
    const int ty = tid >> 4;

    if (tid < BM) {
        int m = m0 + tid;
        rowtok[tid] = (m < ne) ? g_list[off + m] : -1;
    }
    __syncthreads();

    const int am = tid >> 1;
    const int ak = (tid & 1) * 4;
    const int bk = tid >> 5;
    const int bn = (tid & 31) * 2;

    const int tok = rowtok[am];
    const float* axp = x + (size_t)(tok < 0 ? 0 : tok) * HDIM + ak;
    const float* wgp = Wg + (size_t)e * HDIM * IDIM + (size_t)bk * IDIM + n0 + bn;
    const float* wup = Wu + (size_t)e * HDIM * IDIM + (size_t)bk * IDIM + n0 + bn;

    float accg[TM][TN];
    float accu[TM][TN];
#pragma unroll
    for (int i = 0; i < TM; i++)
#pragma unroll
        for (int j = 0; j < TN; j++) { accg[i][j] = 0.f; accu[i][j] = 0.f; }

    for (int k0 = 0; k0 < HDIM; k0 += BK) {
        float4 av = make_float4(0.f, 0.f, 0.f, 0.f);
        if (tok >= 0) av = *(const float4*)(axp + k0);
        As[ak + 0][am] = av.x; As[ak + 1][am] = av.y;
        As[ak + 2][am] = av.z; As[ak + 3][am] = av.w;

        float2 gv = *(const float2*)(wgp + (size_t)k0 * IDIM);
        float2 uv = *(const float2*)(wup + (size_t)k0 * IDIM);
        Bg[bk][bn] = gv.x; Bg[bk][bn + 1] = gv.y;
        Bu[bk][bn] = uv.x; Bu[bk][bn + 1] = uv.y;
        __syncthreads();

#pragma unroll
        for (int k = 0; k < BK; k++) {
            float a[TM], bg[TN], bu[TN];
#pragma unroll
            for (int i = 0; i < TM; i++) a[i] = As[k][ty * TM + i];
#pragma unroll
            for (int j = 0; j < TN; j++) { bg[j] = Bg[k][tx * TN + j]; bu[j] = Bu[k][tx * TN + j]; }
#pragma unroll
            for (int i = 0; i < TM; i++)
#pragma unroll
                for (int j = 0; j < TN; j++) {
                    accg[i][j] += a[i] * bg[j];
                    accu[i][j] += a[i] * bu[j];
                }
        }
        __syncthreads();
    }

#pragma unroll
    for (int i = 0; i < TM; i++) {
        int m = m0 + ty * TM + i;
        if (m >= ne) continue;
        float4 v;
        float g, u;
        g = accg[i][0]; u = accu[i][0]; v.x = (g / (1.f + expf(-g))) * u;
        g = accg[i][1]; u = accu[i][1]; v.y = (g / (1.f + expf(-g))) * u;
        g = accg[i][2]; u = accu[i][2]; v.z = (g / (1.f + expf(-g))) * u;
        g = accg[i][3]; u = accu[i][3]; v.w = (g / (1.f + expf(-g))) * u;
        *(float4*)(g_act + (size_t)(off + m) * IDIM + n0 + tx * TN) = v;
    }
}

// Down grouped GEMM with per-pair weight -> g_pairout
// grid: (HDIM/BN, 32, EDIM), 256 threads
__global__ __launch_bounds__(256, 2) void down_kernel(const float* __restrict__ Wd) {
    const int e = blockIdx.z;
    const int ne = g_cnt[e];
    const int m0 = blockIdx.y * BM;
    if (m0 >= ne) return;
    const int n0 = blockIdx.x * BN;
    const int off = g_off[e];

    __shared__ float As[BK][BM];
    __shared__ float Bs[BK][BN];

    const int tid = threadIdx.x;
    const int tx = tid & 15;
    const int ty = tid >> 4;

    const int am = tid >> 1;
    const int ak = (tid & 1) * 4;
    const int bk = tid >> 5;
    const int bn = (tid & 31) * 2;

    const bool arow_ok = (m0 + am) < ne;
    const float* ap = g_act + (size_t)(off + m0 + (arow_ok ? am : 0)) * IDIM + ak;
    const float* wdp = Wd + (size_t)e * IDIM * HDIM + (size_t)bk * HDIM + n0 + bn;

    float acc[TM][TN];
#pragma unroll
    for (int i = 0; i < TM; i++)
#pragma unroll
        for (int j = 0; j < TN; j++) acc[i][j] = 0.f;

    for (int k0 = 0; k0 < IDIM; k0 += BK) {
        float4 av = make_float4(0.f, 0.f, 0.f, 0.f);
        if (arow_ok) av = *(const float4*)(ap + k0);
        As[ak + 0][am] = av.x; As[ak + 1][am] = av.y;
        As[ak + 2][am] = av.z; As[ak + 3][am] = av.w;

        float2 bv = *(const float2*)(wdp + (size_t)k0 * HDIM);
        Bs[bk][bn] = bv.x; Bs[bk][bn + 1] = bv.y;
        __syncthreads();

#pragma unroll
        for (int k = 0; k < BK; k++) {
            float a[TM], b[TN];
#pragma unroll
            for (int i = 0; i < TM; i++) a[i] = As[k][ty * TM + i];
#pragma unroll
            for (int j = 0; j < TN; j++) b[j] = Bs[k][tx * TN + j];
#pragma unroll
            for (int i = 0; i < TM; i++)
#pragma unroll
                for (int j = 0; j < TN; j++) acc[i][j] += a[i] * b[j];
        }
        __syncthreads();
    }

#pragma unroll
    for (int i = 0; i < TM; i++) {
        int m = m0 + ty * TM + i;
        if (m >= ne) continue;
        float wt = g_wt[off + m];
        float4 v;
        v.x = wt * acc[i][0]; v.y = wt * acc[i][1];
        v.z = wt * acc[i][2]; v.w = wt * acc[i][3];
        *(float4*)(g_pairout + (size_t)(off + m) * HDIM + n0 + tx * TN) = v;
    }
}

// out[t, :] = pairout[p0, :] + pairout[p1, :]   (weights already applied)
__global__ void combine_kernel(float* __restrict__ out) {
    int idx = blockIdx.x * blockDim.x + threadIdx.x;  // over T*H/4
    int t = idx >> 8;       // H/4 = 256
    int h4 = idx & 255;
    int p0 = g_tokpair[t * 2 + 0];
    int p1 = g_tokpair[t * 2 + 1];
    const float4* po = (const float4*)g_pairout;
    float4 a = po[(size_t)p0 * 256 + h4];
    float4 b = po[(size_t)p1 * 256 + h4];
    float4 r;
    r.x = a.x + b.x; r.y = a.y + b.y; r.z = a.z + b.z; r.w = a.w + b.w;
    ((float4*)out)[idx] = r;
}

// ---------------- launch ----------------
extern "C" void kernel_launch(void* const* d_in, const int* in_sizes, int n_in,
                              void* d_out, int out_size) {
    const float* x  = (const float*)d_in[0];
    const float* gw = (const float*)d_in[1];
    const float* Wg = (const float*)d_in[2];
    const float* Wu = (const float*)d_in[3];
    const float* Wd = (const float*)d_in[4];
    float* out = (float*)d_out;
    float* out_logits = out + (size_t)T_TOK * HDIM;

    zero_kernel<<<1, 32>>>();
    router_kernel<<<T_TOK, 128>>>(x, gw, out_logits);
    scan_kernel<<<1, 1>>>();
    assign_kernel<<<T_TOK / 256, 256>>>();
    gateup_kernel<<<dim3(IDIM / BN, T_TOK / BM, EDIM), 256>>>(x, Wg, Wu);
    down_kernel<<<dim3(HDIM / BN, T_TOK / BM, EDIM), 256>>>(Wd);
    combine_kernel<<<(T_TOK * HDIM / 4) / 256, 256>>>(out);
}

// round 5
// speedup vs baseline: 2.0146x; 2.0146x over previous
#include <cuda_runtime.h>
#include <cstdint>
#include <math.h>

// Problem constants
#define T_TOK 4096      // B*S
#define HDIM  1024
#define IDIM  2816
#define EDIM  8
#define TOPK  2
#define NPAIR (T_TOK*TOPK)   // 8192

#define KC    32        // K-chunk per stage
#define BMT   128       // CTA M tile
#define BNT   128       // CTA N tile
#define PADA  36        // A smem row pitch (floats): bank-conflict-free fragments
#define PADB  136       // B smem row pitch (floats)
#define A_FL  (BMT*PADA)   // 4608 floats
#define B_FL  (KC*PADB)    // 4352 floats

// ---------------- scratch (__device__ globals: alloc-free) ----------------
__device__ int   g_cnt[EDIM];
__device__ int   g_off[EDIM + 1];
__device__ int   g_fill[EDIM];
__device__ int   g_tok_e[NPAIR];
__device__ float g_tok_w[NPAIR];
__device__ int   g_list[NPAIR];
__device__ float g_wt[NPAIR];
__device__ int   g_tokpair[NPAIR];
__device__ float g_act[(size_t)NPAIR * IDIM];      // 92.3 MB
__device__ float g_pairout[(size_t)NPAIR * HDIM];  // 33.5 MB

// ---------------- helpers ----------------
__device__ __forceinline__ uint32_t f2tf32(float f) {
    uint32_t r;
    asm("cvt.rna.tf32.f32 %0, %1;" : "=r"(r) : "f"(f));
    return r;
}
__device__ __forceinline__ float tf32f(float f) {
    return __uint_as_float(f2tf32(f));
}
__device__ __forceinline__ void mma_tf32(float* d, const uint32_t* a, const uint32_t* b) {
    asm volatile(
        "mma.sync.aligned.m16n8k8.row.col.f32.tf32.tf32.f32 "
        "{%0,%1,%2,%3}, {%4,%5,%6,%7}, {%8,%9}, {%0,%1,%2,%3};"
        : "+f"(d[0]), "+f"(d[1]), "+f"(d[2]), "+f"(d[3])
        : "r"(a[0]), "r"(a[1]), "r"(a[2]), "r"(a[3]), "r"(b[0]), "r"(b[1]));
}

// ---------------- routing kernels ----------------
__global__ void zero_kernel() {
    int i = threadIdx.x;
    if (i < EDIM) g_cnt[i] = 0;
}

__global__ void router_kernel(const float* __restrict__ x,
                              const float* __restrict__ gw,
                              float* __restrict__ out_logits) {
    const int t = blockIdx.x;
    const int tid = threadIdx.x;
    float acc[EDIM];
#pragma unroll
    for (int e = 0; e < EDIM; e++) acc[e] = 0.f;
    const float* xr = x + (size_t)t * HDIM;
    for (int h = tid; h < HDIM; h += 128) {
        float xv = xr[h];
        const float* gr = gw + (size_t)h * EDIM;
#pragma unroll
        for (int e = 0; e < EDIM; e++) acc[e] += xv * gr[e];
    }
    __shared__ float red[EDIM][128];
#pragma unroll
    for (int e = 0; e < EDIM; e++) red[e][tid] = acc[e];
    __syncthreads();
    for (int s = 64; s > 0; s >>= 1) {
        if (tid < s) {
#pragma unroll
            for (int e = 0; e < EDIM; e++) red[e][tid] += red[e][tid + s];
        }
        __syncthreads();
    }
    if (tid == 0) {
        float l[EDIM];
#pragma unroll
        for (int e = 0; e < EDIM; e++) {
            l[e] = red[e][0];
            out_logits[(size_t)t * EDIM + e] = l[e];
        }
        int i0 = 0;
#pragma unroll
        for (int e = 1; e < EDIM; e++) if (l[e] > l[i0]) i0 = e;
        int i1 = -1;
#pragma unroll
        for (int e = 0; e < EDIM; e++) {
            if (e == i0) continue;
            if (i1 < 0 || l[e] > l[i1]) i1 = e;
        }
        float e1 = expf(l[i1] - l[i0]);
        float w0 = 1.f / (1.f + e1);
        float w1 = e1 / (1.f + e1);
        g_tok_e[t * 2 + 0] = i0; g_tok_w[t * 2 + 0] = w0;
        g_tok_e[t * 2 + 1] = i1; g_tok_w[t * 2 + 1] = w1;
        atomicAdd(&g_cnt[i0], 1);
        atomicAdd(&g_cnt[i1], 1);
    }
}

__global__ void scan_kernel() {
    int s = 0;
    for (int e = 0; e < EDIM; e++) {
        g_off[e] = s;
        s += g_cnt[e];
        g_fill[e] = 0;
    }
    g_off[EDIM] = s;
}

__global__ void assign_kernel() {
    int t = blockIdx.x * blockDim.x + threadIdx.x;
    if (t >= T_TOK) return;
#pragma unroll
    for (int k = 0; k < TOPK; k++) {
        int e = g_tok_e[t * 2 + k];
        int slot = atomicAdd(&g_fill[e], 1);
        int p = g_off[e] + slot;
        g_list[p] = t;
        g_wt[p] = g_tok_w[t * 2 + k];
        g_tokpair[t * 2 + k] = p;
    }
}

// ---------------- fused gate+up grouped GEMM (tf32 mma.sync) ----------------
// grid: (IDIM/128=22, NPAIR/128=64, EDIM), 256 threads
// SMEM floats: rowtok[128] | {A(4608) G(4352) U(4352)} x2
#define GU_SMEM ((128 + 2 * (A_FL + 2 * B_FL)) * 4)

__global__ __launch_bounds__(256, 1) void gateup_tc(
    const float* __restrict__ x,
    const float* __restrict__ Wg,
    const float* __restrict__ Wu) {
    extern __shared__ float sm[];
    const int e = blockIdx.z;
    const int ne = g_cnt[e];
    const int m0 = blockIdx.y * BMT;
    if (m0 >= ne) return;
    const int n0 = blockIdx.x * BNT;
    const int off = g_off[e];

    int* rowtok = (int*)sm;
    const int tid = threadIdx.x;
    const int wid = tid >> 5;
    const int lane = tid & 31;

    if (tid < BMT) {
        int m = m0 + tid;
        rowtok[tid] = g_list[off + (m < ne ? m : 0)];
    }
    __syncthreads();

    // staging addresses
    const int ac4 = (tid & 7) * 4;           // A col (floats)
    const int bc4 = (tid & 31) * 4;          // B col
    const int br  = tid >> 5;                // B base row (stride 8)
    const float* aptr[4];
#pragma unroll
    for (int i = 0; i < 4; i++) {
        int r = i * 32 + (tid >> 3);
        aptr[i] = x + (size_t)rowtok[r] * HDIM + ac4;
    }
    const float* gptr = Wg + (size_t)e * HDIM * IDIM + (size_t)br * IDIM + n0 + bc4;
    const float* uptr = Wu + (size_t)e * HDIM * IDIM + (size_t)br * IDIM + n0 + bc4;

    float* bufA[2] = { sm + 128, sm + 128 + (A_FL + 2 * B_FL) };
    float* bufG[2] = { bufA[0] + A_FL, bufA[1] + A_FL };
    float* bufU[2] = { bufG[0] + B_FL, bufG[1] + B_FL };

    // accumulators
    float accg[4][4][4], accu[4][4][4];
#pragma unroll
    for (int i = 0; i < 4; i++)
#pragma unroll
        for (int j = 0; j < 4; j++)
#pragma unroll
            for (int q = 0; q < 4; q++) { accg[i][j][q] = 0.f; accu[i][j][q] = 0.f; }

    const int m0w = (wid >> 2) * 64;   // warp m offset in tile
    const int n0w = (wid & 3) * 32;    // warp n offset in tile

    float4 pa[4], pg[4], pu[4];
    // prefetch chunk 0
#pragma unroll
    for (int i = 0; i < 4; i++) {
        pa[i] = *(const float4*)(aptr[i]);
        pg[i] = *(const float4*)(gptr + (size_t)(i * 8) * IDIM);
        pu[i] = *(const float4*)(uptr + (size_t)(i * 8) * IDIM);
    }
    // store chunk 0
#pragma unroll
    for (int i = 0; i < 4; i++) {
        int ra = i * 32 + (tid >> 3);
        float* da = bufA[0] + ra * PADA + ac4;
        da[0] = tf32f(pa[i].x); da[1] = tf32f(pa[i].y); da[2] = tf32f(pa[i].z); da[3] = tf32f(pa[i].w);
        int rb = i * 8 + br;
        float* dg = bufG[0] + rb * PADB + bc4;
        dg[0] = tf32f(pg[i].x); dg[1] = tf32f(pg[i].y); dg[2] = tf32f(pg[i].z); dg[3] = tf32f(pg[i].w);
        float* du = bufU[0] + rb * PADB + bc4;
        du[0] = tf32f(pu[i].x); du[1] = tf32f(pu[i].y); du[2] = tf32f(pu[i].z); du[3] = tf32f(pu[i].w);
    }
    __syncthreads();

    const int NCH = HDIM / KC;  // 32
#pragma unroll 1
    for (int kc = 0; kc < NCH; kc++) {
        const int buf = kc & 1;
        if (kc + 1 < NCH) {
            int k0n = (kc + 1) * KC;
#pragma unroll
            for (int i = 0; i < 4; i++) {
                pa[i] = *(const float4*)(aptr[i] + k0n);
                pg[i] = *(const float4*)(gptr + (size_t)(k0n + i * 8) * IDIM);
                pu[i] = *(const float4*)(uptr + (size_t)(k0n + i * 8) * IDIM);
            }
        }
        // compute on buf
        const float* sA = bufA[buf];
        const float* sG = bufG[buf];
        const float* sU = bufU[buf];
        const int r0 = lane >> 2;
        const int kq = lane & 3;
        const int nq = lane >> 2;
#pragma unroll
        for (int k8 = 0; k8 < KC; k8 += 8) {
            uint32_t af[4][4];
#pragma unroll
            for (int mt = 0; mt < 4; mt++) {
                const float* ab = sA + (m0w + mt * 16 + r0) * PADA + k8 + kq;
                af[mt][0] = __float_as_uint(ab[0]);
                af[mt][1] = __float_as_uint(ab[8 * PADA]);
                af[mt][2] = __float_as_uint(ab[4]);
                af[mt][3] = __float_as_uint(ab[8 * PADA + 4]);
            }
#pragma unroll
            for (int nt = 0; nt < 4; nt++) {
                const float* gb = sG + (k8 + kq) * PADB + n0w + nt * 8 + nq;
                uint32_t bg[2] = { __float_as_uint(gb[0]), __float_as_uint(gb[4 * PADB]) };
                const float* ub = sU + (k8 + kq) * PADB + n0w + nt * 8 + nq;
                uint32_t bu[2] = { __float_as_uint(ub[0]), __float_as_uint(ub[4 * PADB]) };
#pragma unroll
                for (int mt = 0; mt < 4; mt++) {
                    mma_tf32(accg[mt][nt], af[mt], bg);
                    mma_tf32(accu[mt][nt], af[mt], bu);
                }
            }
        }
        __syncthreads();
        if (kc + 1 < NCH) {
            float* dA = bufA[buf ^ 1];
            float* dG = bufG[buf ^ 1];
            float* dU = bufU[buf ^ 1];
#pragma unroll
            for (int i = 0; i < 4; i++) {
                int ra = i * 32 + (tid >> 3);
                float* da = dA + ra * PADA + ac4;
                da[0] = tf32f(pa[i].x); da[1] = tf32f(pa[i].y); da[2] = tf32f(pa[i].z); da[3] = tf32f(pa[i].w);
                int rb = i * 8 + br;
                float* dg = dG + rb * PADB + bc4;
                dg[0] = tf32f(pg[i].x); dg[1] = tf32f(pg[i].y); dg[2] = tf32f(pg[i].z); dg[3] = tf32f(pg[i].w);
                float* du = dU + rb * PADB + bc4;
                du[0] = tf32f(pu[i].x); du[1] = tf32f(pu[i].y); du[2] = tf32f(pu[i].z); du[3] = tf32f(pu[i].w);
            }
        }
        __syncthreads();
    }

    // epilogue: SwiGLU -> g_act
#pragma unroll
    for (int mt = 0; mt < 4; mt++) {
        int rloc = m0w + mt * 16 + (lane >> 2);
#pragma unroll
        for (int h = 0; h < 2; h++) {
            int m = m0 + rloc + h * 8;
            if (m < ne) {
                float* orow = g_act + (size_t)(off + m) * IDIM + n0;
#pragma unroll
                for (int nt = 0; nt < 4; nt++) {
                    int c = n0w + nt * 8 + 2 * (lane & 3);
                    float gg0 = accg[mt][nt][2 * h], gg1 = accg[mt][nt][2 * h + 1];
                    float uu0 = accu[mt][nt][2 * h], uu1 = accu[mt][nt][2 * h + 1];
                    float2 v;
                    v.x = gg0 / (1.f + expf(-gg0)) * uu0;
                    v.y = gg1 / (1.f + expf(-gg1)) * uu1;
                    *(float2*)(orow + c) = v;
                }
            }
        }
    }
}

// ---------------- down grouped GEMM (tf32 mma.sync) ----------------
// grid: (HDIM/128=8, NPAIR/128=64, EDIM), 256 threads
#define DN_SMEM ((2 * (A_FL + B_FL)) * 4)

__global__ __launch_bounds__(256, 1) void down_tc(const float* __restrict__ Wd) {
    extern __shared__ float sm[];
    const int e = blockIdx.z;
    const int ne = g_cnt[e];
    const int m0 = blockIdx.y * BMT;
    if (m0 >= ne) return;
    const int n0 = blockIdx.x * BNT;
    const int off = g_off[e];

    const int tid = threadIdx.x;
    const int wid = tid >> 5;
    const int lane = tid & 31;

    const int ac4 = (tid & 7) * 4;
    const int bc4 = (tid & 31) * 4;
    const int br  = tid >> 5;
    const float* aptr[4];
#pragma unroll
    for (int i = 0; i < 4; i++) {
        int r = i * 32 + (tid >> 3);
        int idx = off + m0 + r;
        if (idx >= NPAIR) idx = NPAIR - 1;
        aptr[i] = g_act + (size_t)idx * IDIM + ac4;
    }
    const float* bptr = Wd + (size_t)e * IDIM * HDIM + (size_t)br * HDIM + n0 + bc4;

    float* bufA[2] = { sm, sm + (A_FL + B_FL) };
    float* bufB[2] = { bufA[0] + A_FL, bufA[1] + A_FL };

    float acc[4][4][4];
#pragma unroll
    for (int i = 0; i < 4; i++)
#pragma unroll
        for (int j = 0; j < 4; j++)
#pragma unroll
            for (int q = 0; q < 4; q++) acc[i][j][q] = 0.f;

    const int m0w = (wid >> 2) * 64;
    const int n0w = (wid & 3) * 32;

    float4 pa[4], pb[4];
#pragma unroll
    for (int i = 0; i < 4; i++) {
        pa[i] = *(const float4*)(aptr[i]);
        pb[i] = *(const float4*)(bptr + (size_t)(i * 8) * HDIM);
    }
#pragma unroll
    for (int i = 0; i < 4; i++) {
        int ra = i * 32 + (tid >> 3);
        float* da = bufA[0] + ra * PADA + ac4;
        da[0] = tf32f(pa[i].x); da[1] = tf32f(pa[i].y); da[2] = tf32f(pa[i].z); da[3] = tf32f(pa[i].w);
        int rb = i * 8 + br;
        float* db = bufB[0] + rb * PADB + bc4;
        db[0] = tf32f(pb[i].x); db[1] = tf32f(pb[i].y); db[2] = tf32f(pb[i].z); db[3] = tf32f(pb[i].w);
    }
    __syncthreads();

    const int NCH = IDIM / KC;  // 88
#pragma unroll 1
    for (int kc = 0; kc < NCH; kc++) {
        const int buf = kc & 1;
        if (kc + 1 < NCH) {
            int k0n = (kc + 1) * KC;
#pragma unroll
            for (int i = 0; i < 4; i++) {
                pa[i] = *(const float4*)(aptr[i] + k0n);
                pb[i] = *(const float4*)(bptr + (size_t)(k0n + i * 8) * HDIM);
            }
        }
        const float* sA = bufA[buf];
        const float* sB = bufB[buf];
        const int r0 = lane >> 2;
        const int kq = lane & 3;
        const int nq = lane >> 2;
#pragma unroll
        for (int k8 = 0; k8 < KC; k8 += 8) {
            uint32_t af[4][4];
#pragma unroll
            for (int mt = 0; mt < 4; mt++) {
                const float* ab = sA + (m0w + mt * 16 + r0) * PADA + k8 + kq;
                af[mt][0] = __float_as_uint(ab[0]);
                af[mt][1] = __float_as_uint(ab[8 * PADA]);
                af[mt][2] = __float_as_uint(ab[4]);
                af[mt][3] = __float_as_uint(ab[8 * PADA + 4]);
            }
#pragma unroll
            for (int nt = 0; nt < 4; nt++) {
                const float* bb = sB + (k8 + kq) * PADB + n0w + nt * 8 + nq;
                uint32_t bf[2] = { __float_as_uint(bb[0]), __float_as_uint(bb[4 * PADB]) };
#pragma unroll
                for (int mt = 0; mt < 4; mt++) {
                    mma_tf32(acc[mt][nt], af[mt], bf);
                }
            }
        }
        __syncthreads();
        if (kc + 1 < NCH) {
            float* dA = bufA[buf ^ 1];
            float* dB = bufB[buf ^ 1];
#pragma unroll
            for (int i = 0; i < 4; i++) {
                int ra = i * 32 + (tid >> 3);
                float* da = dA + ra * PADA + ac4;
                da[0] = tf32f(pa[i].x); da[1] = tf32f(pa[i].y); da[2] = tf32f(pa[i].z); da[3] = tf32f(pa[i].w);
                int rb = i * 8 + br;
                float* db = dB + rb * PADB + bc4;
                db[0] = tf32f(pb[i].x); db[1] = tf32f(pb[i].y); db[2] = tf32f(pb[i].z); db[3] = tf32f(pb[i].w);
            }
        }
        __syncthreads();
    }

    // epilogue: weight and store to g_pairout
#pragma unroll
    for (int mt = 0; mt < 4; mt++) {
        int rloc = m0w + mt * 16 + (lane >> 2);
#pragma unroll
        for (int h = 0; h < 2; h++) {
            int m = m0 + rloc + h * 8;
            if (m < ne) {
                float wt = g_wt[off + m];
                float* orow = g_pairout + (size_t)(off + m) * HDIM + n0;
#pragma unroll
                for (int nt = 0; nt < 4; nt++) {
                    int c = n0w + nt * 8 + 2 * (lane & 3);
                    float2 v;
                    v.x = wt * acc[mt][nt][2 * h];
                    v.y = wt * acc[mt][nt][2 * h + 1];
                    *(float2*)(orow + c) = v;
                }
            }
        }
    }
}

// out[t, :] = pairout[p0, :] + pairout[p1, :]
__global__ void combine_kernel(float* __restrict__ out) {
    int idx = blockIdx.x * blockDim.x + threadIdx.x;
    int t = idx >> 8;
    int h4 = idx & 255;
    int p0 = g_tokpair[t * 2 + 0];
    int p1 = g_tokpair[t * 2 + 1];
    const float4* po = (const float4*)g_pairout;
    float4 a = po[(size_t)p0 * 256 + h4];
    float4 b = po[(size_t)p1 * 256 + h4];
    float4 r;
    r.x = a.x + b.x; r.y = a.y + b.y; r.z = a.z + b.z; r.w = a.w + b.w;
    ((float4*)out)[idx] = r;
}

// ---------------- launch ----------------
extern "C" void kernel_launch(void* const* d_in, const int* in_sizes, int n_in,
                              void* d_out, int out_size) {
    const float* x  = (const float*)d_in[0];
    const float* gw = (const float*)d_in[1];
    const float* Wg = (const float*)d_in[2];
    const float* Wu = (const float*)d_in[3];
    const float* Wd = (const float*)d_in[4];
    float* out = (float*)d_out;
    float* out_logits = out + (size_t)T_TOK * HDIM;

    cudaFuncSetAttribute(gateup_tc, cudaFuncAttributeMaxDynamicSharedMemorySize, GU_SMEM);
    cudaFuncSetAttribute(down_tc, cudaFuncAttributeMaxDynamicSharedMemorySize, DN_SMEM);

    zero_kernel<<<1, 32>>>();
    router_kernel<<<T_TOK, 128>>>(x, gw, out_logits);
    scan_kernel<<<1, 1>>>();
    assign_kernel<<<T_TOK / 256, 256>>>();
    gateup_tc<<<dim3(IDIM / BNT, NPAIR / BMT, EDIM), 256, GU_SMEM>>>(x, Wg, Wu);
    down_tc<<<dim3(HDIM / BNT, NPAIR / BMT, EDIM), 256, DN_SMEM>>>(Wd);
    combine_kernel<<<(T_TOK * HDIM / 4) / 256, 256>>>(out);
}

// round 6
// speedup vs baseline: 2.0982x; 1.0415x over previous
#include <cuda_runtime.h>
#include <cstdint>
#include <math.h>

// Problem constants
#define T_TOK 4096      // B*S
#define HDIM  1024
#define IDIM  2816
#define EDIM  8
#define TOPK  2
#define NPAIR (T_TOK*TOPK)   // 8192

#define KC    32        // K-chunk per stage
#define BMT   128       // CTA M tile
#define BNT   128       // CTA N tile
#define PADA  36        // A smem row pitch (floats): bank-conflict-free fragments
#define PADB  136       // B smem row pitch (floats)
#define A_FL  (BMT*PADA)   // 4608 floats
#define B_FL  (KC*PADB)    // 4352 floats

// ---------------- scratch (__device__ globals: alloc-free) ----------------
__device__ int   g_cnt[EDIM];        // zero-init at load; scan re-zeroes each call
__device__ int   g_off[EDIM + 1];
__device__ int   g_fill[EDIM];
__device__ int   g_tok_e[NPAIR];
__device__ float g_tok_w[NPAIR];
__device__ int   g_list[NPAIR];
__device__ float g_wt[NPAIR];
__device__ int   g_tokpair[NPAIR];
__device__ float g_act[(size_t)NPAIR * IDIM];      // 92.3 MB
__device__ float g_pairout[(size_t)NPAIR * HDIM];  // 33.5 MB

// ---------------- helpers ----------------
__device__ __forceinline__ uint32_t f2tf32(float f) {
    uint32_t r;
    asm("cvt.rna.tf32.f32 %0, %1;" : "=r"(r) : "f"(f));
    return r;
}
__device__ __forceinline__ float tf32f(float f) {
    return __uint_as_float(f2tf32(f));
}
__device__ __forceinline__ void mma_tf32(float* d, const uint32_t* a, const uint32_t* b) {
    asm volatile(
        "mma.sync.aligned.m16n8k8.row.col.f32.tf32.tf32.f32 "
        "{%0,%1,%2,%3}, {%4,%5,%6,%7}, {%8,%9}, {%0,%1,%2,%3};"
        : "+f"(d[0]), "+f"(d[1]), "+f"(d[2]), "+f"(d[3])
        : "r"(a[0]), "r"(a[1]), "r"(a[2]), "r"(a[3]), "r"(b[0]), "r"(b[1]));
}

// ---------------- routing kernels ----------------
__global__ void router_kernel(const float* __restrict__ x,
                              const float* __restrict__ gw,
                              float* __restrict__ out_logits) {
    const int t = blockIdx.x;
    const int tid = threadIdx.x;
    float acc[EDIM];
#pragma unroll
    for (int e = 0; e < EDIM; e++) acc[e] = 0.f;
    const float* xr = x + (size_t)t * HDIM;
    for (int h = tid; h < HDIM; h += 128) {
        float xv = xr[h];
        const float* gr = gw + (size_t)h * EDIM;
#pragma unroll
        for (int e = 0; e < EDIM; e++) acc[e] += xv * gr[e];
    }
    __shared__ float red[EDIM][128];
#pragma unroll
    for (int e = 0; e < EDIM; e++) red[e][tid] = acc[e];
    __syncthreads();
    for (int s = 64; s > 0; s >>= 1) {
        if (tid < s) {
#pragma unroll
            for (int e = 0; e < EDIM; e++) red[e][tid] += red[e][tid + s];
        }
        __syncthreads();
    }
    if (tid == 0) {
        float l[EDIM];
#pragma unroll
        for (int e = 0; e < EDIM; e++) {
            l[e] = red[e][0];
            out_logits[(size_t)t * EDIM + e] = l[e];
        }
        int i0 = 0;
#pragma unroll
        for (int e = 1; e < EDIM; e++) if (l[e] > l[i0]) i0 = e;
        int i1 = -1;
#pragma unroll
        for (int e = 0; e < EDIM; e++) {
            if (e == i0) continue;
            if (i1 < 0 || l[e] > l[i1]) i1 = e;
        }
        float e1 = expf(l[i1] - l[i0]);
        float w0 = 1.f / (1.f + e1);
        float w1 = e1 / (1.f + e1);
        g_tok_e[t * 2 + 0] = i0; g_tok_w[t * 2 + 0] = w0;
        g_tok_e[t * 2 + 1] = i1; g_tok_w[t * 2 + 1] = w1;
        atomicAdd(&g_cnt[i0], 1);
        atomicAdd(&g_cnt[i1], 1);
    }
}

// scan + reset g_cnt for next graph replay (globals are zero-init at load,
// so the first call sees zeros too; GEMMs read counts via g_off diffs)
__global__ void scan_kernel() {
    int s = 0;
    for (int e = 0; e < EDIM; e++) {
        g_off[e] = s;
        s += g_cnt[e];
        g_fill[e] = 0;
        g_cnt[e] = 0;
    }
    g_off[EDIM] = s;
}

__global__ void assign_kernel() {
    int t = blockIdx.x * blockDim.x + threadIdx.x;
    if (t >= T_TOK) return;
#pragma unroll
    for (int k = 0; k < TOPK; k++) {
        int e = g_tok_e[t * 2 + k];
        int slot = atomicAdd(&g_fill[e], 1);
        int p = g_off[e] + slot;
        g_list[p] = t;
        g_wt[p] = g_tok_w[t * 2 + k];
        g_tokpair[t * 2 + k] = p;
    }
}

// ---------------- fused gate+up grouped GEMM (tf32 mma.sync) ----------------
// grid: (IDIM/128=22, NPAIR/128=64, EDIM), 256 threads
#define GU_SMEM ((128 + 2 * (A_FL + 2 * B_FL)) * 4)

__global__ __launch_bounds__(256, 1) void gateup_tc(
    const float* __restrict__ x,
    const float* __restrict__ Wg,
    const float* __restrict__ Wu) {
    extern __shared__ float sm[];
    const int e = blockIdx.z;
    const int ne = g_off[e + 1] - g_off[e];
    const int m0 = blockIdx.y * BMT;
    if (m0 >= ne) return;
    const int n0 = blockIdx.x * BNT;
    const int off = g_off[e];

    int* rowtok = (int*)sm;
    const int tid = threadIdx.x;
    const int wid = tid >> 5;
    const int lane = tid & 31;

    if (tid < BMT) {
        int m = m0 + tid;
        rowtok[tid] = g_list[off + (m < ne ? m : 0)];
    }
    __syncthreads();

    const int ac4 = (tid & 7) * 4;
    const int bc4 = (tid & 31) * 4;
    const int br  = tid >> 5;
    const float* aptr[4];
#pragma unroll
    for (int i = 0; i < 4; i++) {
        int r = i * 32 + (tid >> 3);
        aptr[i] = x + (size_t)rowtok[r] * HDIM + ac4;
    }
    const float* gptr = Wg + (size_t)e * HDIM * IDIM + (size_t)br * IDIM + n0 + bc4;
    const float* uptr = Wu + (size_t)e * HDIM * IDIM + (size_t)br * IDIM + n0 + bc4;

    float* bufA[2] = { sm + 128, sm + 128 + (A_FL + 2 * B_FL) };
    float* bufG[2] = { bufA[0] + A_FL, bufA[1] + A_FL };
    float* bufU[2] = { bufG[0] + B_FL, bufG[1] + B_FL };

    float accg[4][4][4], accu[4][4][4];
#pragma unroll
    for (int i = 0; i < 4; i++)
#pragma unroll
        for (int j = 0; j < 4; j++)
#pragma unroll
            for (int q = 0; q < 4; q++) { accg[i][j][q] = 0.f; accu[i][j][q] = 0.f; }

    const int m0w = (wid >> 2) * 64;
    const int n0w = (wid & 3) * 32;

    float4 pa[4], pg[4], pu[4];
    // load + store chunk 0
#pragma unroll
    for (int i = 0; i < 4; i++) {
        pa[i] = *(const float4*)(aptr[i]);
        pg[i] = *(const float4*)(gptr + (size_t)(i * 8) * IDIM);
        pu[i] = *(const float4*)(uptr + (size_t)(i * 8) * IDIM);
    }
#pragma unroll
    for (int i = 0; i < 4; i++) {
        int ra = i * 32 + (tid >> 3);
        float* da = bufA[0] + ra * PADA + ac4;
        da[0] = tf32f(pa[i].x); da[1] = tf32f(pa[i].y); da[2] = tf32f(pa[i].z); da[3] = tf32f(pa[i].w);
        int rb = i * 8 + br;
        float* dg = bufG[0] + rb * PADB + bc4;
        dg[0] = tf32f(pg[i].x); dg[1] = tf32f(pg[i].y); dg[2] = tf32f(pg[i].z); dg[3] = tf32f(pg[i].w);
        float* du = bufU[0] + rb * PADB + bc4;
        du[0] = tf32f(pu[i].x); du[1] = tf32f(pu[i].y); du[2] = tf32f(pu[i].z); du[3] = tf32f(pu[i].w);
    }
    __syncthreads();

    const int NCH = HDIM / KC;  // 32
#pragma unroll 1
    for (int kc = 0; kc < NCH; kc++) {
        const int buf = kc & 1;
        const bool more = (kc + 1 < NCH);
        if (more) {
            int k0n = (kc + 1) * KC;
#pragma unroll
            for (int i = 0; i < 4; i++) {
                pa[i] = *(const float4*)(aptr[i] + k0n);
                pg[i] = *(const float4*)(gptr + (size_t)(k0n + i * 8) * IDIM);
                pu[i] = *(const float4*)(uptr + (size_t)(k0n + i * 8) * IDIM);
            }
        }
        // compute on buf
        const float* sA = bufA[buf];
        const float* sG = bufG[buf];
        const float* sU = bufU[buf];
        const int r0 = lane >> 2;
        const int kq = lane & 3;
        const int nq = lane >> 2;
#pragma unroll
        for (int k8 = 0; k8 < KC; k8 += 8) {
            uint32_t af[4][4];
#pragma unroll
            for (int mt = 0; mt < 4; mt++) {
                const float* ab = sA + (m0w + mt * 16 + r0) * PADA + k8 + kq;
                af[mt][0] = __float_as_uint(ab[0]);
                af[mt][1] = __float_as_uint(ab[8 * PADA]);
                af[mt][2] = __float_as_uint(ab[4]);
                af[mt][3] = __float_as_uint(ab[8 * PADA + 4]);
            }
#pragma unroll
            for (int nt = 0; nt < 4; nt++) {
                const float* gb = sG + (k8 + kq) * PADB + n0w + nt * 8 + nq;
                uint32_t bg[2] = { __float_as_uint(gb[0]), __float_as_uint(gb[4 * PADB]) };
                const float* ub = sU + (k8 + kq) * PADB + n0w + nt * 8 + nq;
                uint32_t bu[2] = { __float_as_uint(ub[0]), __float_as_uint(ub[4 * PADB]) };
#pragma unroll
                for (int mt = 0; mt < 4; mt++) {
                    mma_tf32(accg[mt][nt], af[mt], bg);
                    mma_tf32(accu[mt][nt], af[mt], bu);
                }
            }
        }
        // store next chunk into the buffer computed last iteration (safe: the
        // sync at the end of the previous iteration drained all its readers)
        if (more) {
            float* dA = bufA[buf ^ 1];
            float* dG = bufG[buf ^ 1];
            float* dU = bufU[buf ^ 1];
#pragma unroll
            for (int i = 0; i < 4; i++) {
                int ra = i * 32 + (tid >> 3);
                float* da = dA + ra * PADA + ac4;
                da[0] = tf32f(pa[i].x); da[1] = tf32f(pa[i].y); da[2] = tf32f(pa[i].z); da[3] = tf32f(pa[i].w);
                int rb = i * 8 + br;
                float* dg = dG + rb * PADB + bc4;
                dg[0] = tf32f(pg[i].x); dg[1] = tf32f(pg[i].y); dg[2] = tf32f(pg[i].z); dg[3] = tf32f(pg[i].w);
                float* du = dU + rb * PADB + bc4;
                du[0] = tf32f(pu[i].x); du[1] = tf32f(pu[i].y); du[2] = tf32f(pu[i].z); du[3] = tf32f(pu[i].w);
            }
        }
        __syncthreads();
    }

    // epilogue: SwiGLU -> g_act
#pragma unroll
    for (int mt = 0; mt < 4; mt++) {
        int rloc = m0w + mt * 16 + (lane >> 2);
#pragma unroll
        for (int h = 0; h < 2; h++) {
            int m = m0 + rloc + h * 8;
            if (m < ne) {
                float* orow = g_act + (size_t)(off + m) * IDIM + n0;
#pragma unroll
                for (int nt = 0; nt < 4; nt++) {
                    int c = n0w + nt * 8 + 2 * (lane & 3);
                    float gg0 = accg[mt][nt][2 * h], gg1 = accg[mt][nt][2 * h + 1];
                    float uu0 = accu[mt][nt][2 * h], uu1 = accu[mt][nt][2 * h + 1];
                    float2 v;
                    v.x = gg0 / (1.f + expf(-gg0)) * uu0;
                    v.y = gg1 / (1.f + expf(-gg1)) * uu1;
                    *(float2*)(orow + c) = v;
                }
            }
        }
    }
}

// ---------------- down grouped GEMM (tf32 mma.sync) ----------------
// grid: (HDIM/128=8, NPAIR/128=64, EDIM), 256 threads, occupancy 2
#define DN_SMEM ((2 * (A_FL + B_FL)) * 4)

__global__ __launch_bounds__(256, 2) void down_tc(const float* __restrict__ Wd) {
    extern __shared__ float sm[];
    const int e = blockIdx.z;
    const int ne = g_off[e + 1] - g_off[e];
    const int m0 = blockIdx.y * BMT;
    if (m0 >= ne) return;
    const int n0 = blockIdx.x * BNT;
    const int off = g_off[e];

    const int tid = threadIdx.x;
    const int wid = tid >> 5;
    const int lane = tid & 31;

    const int ac4 = (tid & 7) * 4;
    const int bc4 = (tid & 31) * 4;
    const int br  = tid >> 5;
    const float* aptr[4];
#pragma unroll
    for (int i = 0; i < 4; i++) {
        int r = i * 32 + (tid >> 3);
        int idx = off + m0 + r;
        if (idx >= NPAIR) idx = NPAIR - 1;
        aptr[i] = g_act + (size_t)idx * IDIM + ac4;
    }
    const float* bptr = Wd + (size_t)e * IDIM * HDIM + (size_t)br * HDIM + n0 + bc4;

    float* bufA[2] = { sm, sm + (A_FL + B_FL) };
    float* bufB[2] = { bufA[0] + A_FL, bufA[1] + A_FL };

    float acc[4][4][4];
#pragma unroll
    for (int i = 0; i < 4; i++)
#pragma unroll
        for (int j = 0; j < 4; j++)
#pragma unroll
            for (int q = 0; q < 4; q++) acc[i][j][q] = 0.f;

    const int m0w = (wid >> 2) * 64;
    const int n0w = (wid & 3) * 32;

    float4 pa[4], pb[4];
#pragma unroll
    for (int i = 0; i < 4; i++) {
        pa[i] = *(const float4*)(aptr[i]);
        pb[i] = *(const float4*)(bptr + (size_t)(i * 8) * HDIM);
    }
#pragma unroll
    for (int i = 0; i < 4; i++) {
        int ra = i * 32 + (tid >> 3);
        float* da = bufA[0] + ra * PADA + ac4;
        da[0] = tf32f(pa[i].x); da[1] = tf32f(pa[i].y); da[2] = tf32f(pa[i].z); da[3] = tf32f(pa[i].w);
        int rb = i * 8 + br;
        float* db = bufB[0] + rb * PADB + bc4;
        db[0] = tf32f(pb[i].x); db[1] = tf32f(pb[i].y); db[2] = tf32f(pb[i].z); db[3] = tf32f(pb[i].w);
    }
    __syncthreads();

    const int NCH = IDIM / KC;  // 88
#pragma unroll 1
    for (int kc = 0; kc < NCH; kc++) {
        const int buf = kc & 1;
        const bool more = (kc + 1 < NCH);
        if (more) {
            int k0n = (kc + 1) * KC;
#pragma unroll
            for (int i = 0; i < 4; i++) {
                pa[i] = *(const float4*)(aptr[i] + k0n);
                pb[i] = *(const float4*)(bptr + (size_t)(k0n + i * 8) * HDIM);
            }
        }
        const float* sA = bufA[buf];
        const float* sB = bufB[buf];
        const int r0 = lane >> 2;
        const int kq = lane & 3;
        const int nq = lane >> 2;
#pragma unroll
        for (int k8 = 0; k8 < KC; k8 += 8) {
            uint32_t af[4][4];
#pragma unroll
            for (int mt = 0; mt < 4; mt++) {
                const float* ab = sA + (m0w + mt * 16 + r0) * PADA + k8 + kq;
                af[mt][0] = __float_as_uint(ab[0]);
                af[mt][1] = __float_as_uint(ab[8 * PADA]);
                af[mt][2] = __float_as_uint(ab[4]);
                af[mt][3] = __float_as_uint(ab[8 * PADA + 4]);
            }
#pragma unroll
            for (int nt = 0; nt < 4; nt++) {
                const float* bb = sB + (k8 + kq) * PADB + n0w + nt * 8 + nq;
                uint32_t bf[2] = { __float_as_uint(bb[0]), __float_as_uint(bb[4 * PADB]) };
#pragma unroll
                for (int mt = 0; mt < 4; mt++) {
                    mma_tf32(acc[mt][nt], af[mt], bf);
                }
            }
        }
        if (more) {
            float* dA = bufA[buf ^ 1];
            float* dB = bufB[buf ^ 1];
#pragma unroll
            for (int i = 0; i < 4; i++) {
                int ra = i * 32 + (tid >> 3);
                float* da = dA + ra * PADA + ac4;
                da[0] = tf32f(pa[i].x); da[1] = tf32f(pa[i].y); da[2] = tf32f(pa[i].z); da[3] = tf32f(pa[i].w);
                int rb = i * 8 + br;
                float* db = dB + rb * PADB + bc4;
                db[0] = tf32f(pb[i].x); db[1] = tf32f(pb[i].y); db[2] = tf32f(pb[i].z); db[3] = tf32f(pb[i].w);
            }
        }
        __syncthreads();
    }

#pragma unroll
    for (int mt = 0; mt < 4; mt++) {
        int rloc = m0w + mt * 16 + (lane >> 2);
#pragma unroll
        for (int h = 0; h < 2; h++) {
            int m = m0 + rloc + h * 8;
            if (m < ne) {
                float wt = g_wt[off + m];
                float* orow = g_pairout + (size_t)(off + m) * HDIM + n0;
#pragma unroll
                for (int nt = 0; nt < 4; nt++) {
                    int c = n0w + nt * 8 + 2 * (lane & 3);
                    float2 v;
                    v.x = wt * acc[mt][nt][2 * h];
                    v.y = wt * acc[mt][nt][2 * h + 1];
                    *(float2*)(orow + c) = v;
                }
            }
        }
    }
}

// out[t, :] = pairout[p0, :] + pairout[p1, :]
__global__ void combine_kernel(float* __restrict__ out) {
    int idx = blockIdx.x * blockDim.x + threadIdx.x;
    int t = idx >> 8;
    int h4 = idx & 255;
    int p0 = g_tokpair[t * 2 + 0];
    int p1 = g_tokpair[t * 2 + 1];
    const float4* po = (const float4*)g_pairout;
    float4 a = po[(size_t)p0 * 256 + h4];
    float4 b = po[(size_t)p1 * 256 + h4];
    float4 r;
    r.x = a.x + b.x; r.y = a.y + b.y; r.z = a.z + b.z; r.w = a.w + b.w;
    ((float4*)out)[idx] = r;
}

// ---------------- launch ----------------
extern "C" void kernel_launch(void* const* d_in, const int* in_sizes, int n_in,
                              void* d_out, int out_size) {
    const float* x  = (const float*)d_in[0];
    const float* gw = (const float*)d_in[1];
    const float* Wg = (const float*)d_in[2];
    const float* Wu = (const float*)d_in[3];
    const float* Wd = (const float*)d_in[4];
    float* out = (float*)d_out;
    float* out_logits = out + (size_t)T_TOK * HDIM;

    cudaFuncSetAttribute(gateup_tc, cudaFuncAttributeMaxDynamicSharedMemorySize, GU_SMEM);
    cudaFuncSetAttribute(down_tc, cudaFuncAttributeMaxDynamicSharedMemorySize, DN_SMEM);

    router_kernel<<<T_TOK, 128>>>(x, gw, out_logits);
    scan_kernel<<<1, 1>>>();
    assign_kernel<<<T_TOK / 256, 256>>>();
    gateup_tc<<<dim3(IDIM / BNT, NPAIR / BMT, EDIM), 256, GU_SMEM>>>(x, Wg, Wu);
    down_tc<<<dim3(HDIM / BNT, NPAIR / BMT, EDIM), 256, DN_SMEM>>>(Wd);
    combine_kernel<<<(T_TOK * HDIM / 4) / 256, 256>>>(out);
}

// round 9
// speedup vs baseline: 3.0831x; 1.4694x over previous
#include <cuda_runtime.h>
#include <cstdint>
#include <math.h>

// Problem constants
#define T_TOK 4096      // B*S
#define HDIM  1024
#define IDIM  2816
#define EDIM  8
#define TOPK  2
#define NPAIR (T_TOK*TOPK)   // 8192

#define KC    32        // K-chunk per stage
#define BMT   128       // CTA M tile
#define BNT   128       // CTA N tile
#define PADA  36        // A smem row pitch (floats)
#define PADB  136       // B smem row pitch (floats)
#define A_FL  (BMT*PADA)   // 4608 floats
#define B_FL  (KC*PADB)    // 4352 floats

// ---------------- scratch (__device__ globals: alloc-free) ----------------
__device__ int   g_cnt[EDIM];        // zero-init at load; scan re-zeroes each call
__device__ int   g_off[EDIM + 1];
__device__ int   g_fill[EDIM];
__device__ int   g_tok_e[NPAIR];
__device__ float g_tok_w[NPAIR];
__device__ int   g_list[NPAIR];
__device__ float g_wt[NPAIR];
__device__ int   g_tokpair[NPAIR];
__device__ float g_raw[(size_t)NPAIR * IDIM];      // raw gate GEMM out, 92.3 MB
__device__ float g_act[(size_t)NPAIR * IDIM];      // swiglu activations, 92.3 MB
__device__ float g_pairout[(size_t)NPAIR * HDIM];  // 33.5 MB

// ---------------- helpers ----------------
__device__ __forceinline__ uint32_t f2tf32(float f) {
    uint32_t r;
    asm("cvt.rna.tf32.f32 %0, %1;" : "=r"(r) : "f"(f));
    return r;
}
__device__ __forceinline__ float tf32f(float f) {
    return __uint_as_float(f2tf32(f));
}
__device__ __forceinline__ void mma_tf32(float* d, const uint32_t* a, const uint32_t* b) {
    asm volatile(
        "mma.sync.aligned.m16n8k8.row.col.f32.tf32.tf32.f32 "
        "{%0,%1,%2,%3}, {%4,%5,%6,%7}, {%8,%9}, {%0,%1,%2,%3};"
        : "+f"(d[0]), "+f"(d[1]), "+f"(d[2]), "+f"(d[3])
        : "r"(a[0]), "r"(a[1]), "r"(a[2]), "r"(a[3]), "r"(b[0]), "r"(b[1]));
}

// ---------------- routing kernels ----------------
__global__ void router_kernel(const float* __restrict__ x,
                              const float* __restrict__ gw,
                              float* __restrict__ out_logits) {
    const int t = blockIdx.x;
    const int tid = threadIdx.x;
    float acc[EDIM];
#pragma unroll
    for (int e = 0; e < EDIM; e++) acc[e] = 0.f;
    const float* xr = x + (size_t)t * HDIM;
    for (int h = tid; h < HDIM; h += 128) {
        float xv = xr[h];
        const float* gr = gw + (size_t)h * EDIM;
#pragma unroll
        for (int e = 0; e < EDIM; e++) acc[e] += xv * gr[e];
    }
    __shared__ float red[EDIM][128];
#pragma unroll
    for (int e = 0; e < EDIM; e++) red[e][tid] = acc[e];
    __syncthreads();
    for (int s = 64; s > 0; s >>= 1) {
        if (tid < s) {
#pragma unroll
            for (int e = 0; e < EDIM; e++) red[e][tid] += red[e][tid + s];
        }
        __syncthreads();
    }
    if (tid == 0) {
        float l[EDIM];
#pragma unroll
        for (int e = 0; e < EDIM; e++) {
            l[e] = red[e][0];
            out_logits[(size_t)t * EDIM + e] = l[e];
        }
        int i0 = 0;
#pragma unroll
        for (int e = 1; e < EDIM; e++) if (l[e] > l[i0]) i0 = e;
        int i1 = -1;
#pragma unroll
        for (int e = 0; e < EDIM; e++) {
            if (e == i0) continue;
            if (i1 < 0 || l[e] > l[i1]) i1 = e;
        }
        float e1 = expf(l[i1] - l[i0]);
        float w0 = 1.f / (1.f + e1);
        float w1 = e1 / (1.f + e1);
        g_tok_e[t * 2 + 0] = i0; g_tok_w[t * 2 + 0] = w0;
        g_tok_e[t * 2 + 1] = i1; g_tok_w[t * 2 + 1] = w1;
        atomicAdd(&g_cnt[i0], 1);
        atomicAdd(&g_cnt[i1], 1);
    }
}

__global__ void scan_kernel() {
    int s = 0;
    for (int e = 0; e < EDIM; e++) {
        g_off[e] = s;
        s += g_cnt[e];
        g_fill[e] = 0;
        g_cnt[e] = 0;
    }
    g_off[EDIM] = s;
}

__global__ void assign_kernel() {
    int t = blockIdx.x * blockDim.x + threadIdx.x;
    if (t >= T_TOK) return;
#pragma unroll
    for (int k = 0; k < TOPK; k++) {
        int e = g_tok_e[t * 2 + k];
        int slot = atomicAdd(&g_fill[e], 1);
        int p = g_off[e] + slot;
        g_list[p] = t;
        g_wt[p] = g_tok_w[t * 2 + k];
        g_tokpair[t * 2 + k] = p;
    }
}

// ============================================================================
// GEMM mainloop core (shared by all three GEMMs)
// Single-buffer smem stage, 8 warps, warp tile 64x32, occ-2 friendly.
// bptr must point at W + n0 (row 0 of the B tile); per-thread row offset
// (br) and column offset (bc4) are applied INSIDE this core.
// ============================================================================
struct GemmCore {
    static __device__ __forceinline__ void run(
        float* sA, float* sB,
        const float* aptr[4], const float* bptr, size_t ldb,
        int NCH, int tid, int wid, int lane,
        float acc[4][4][4]) {
        const int ac4 = (tid & 7) * 4;
        const int ar  = tid >> 3;            // 0..31, A row within 32-row group
        const int bc4 = (tid & 31) * 4;
        const int br  = tid >> 5;            // 0..7
        const int m0w = (wid >> 2) * 64;
        const int n0w = (wid & 3) * 32;
        const int r0 = lane >> 2;
        const int kq = lane & 3;
        const int nq = lane >> 2;

        // per-thread B pointer: row br, col bc4 of the CTA's B tile
        const float* bp = bptr + (size_t)br * ldb + bc4;

        float4 vb[4];
#pragma unroll
        for (int i = 0; i < 4; i++)
            vb[i] = *(const float4*)(bp + (size_t)(i * 8) * ldb);

#pragma unroll 1
        for (int kc = 0; kc < NCH; kc++) {
            const int k0 = kc * KC;
            // A loads (L2-mostly-hot) + immediate store
            float4 va[4];
#pragma unroll
            for (int i = 0; i < 4; i++)
                va[i] = *(const float4*)(aptr[i] + k0);
#pragma unroll
            for (int i = 0; i < 4; i++) {
                int ra = i * 32 + ar;
                float* da = sA + ra * PADA + ac4;
                da[0] = tf32f(va[i].x); da[1] = tf32f(va[i].y);
                da[2] = tf32f(va[i].z); da[3] = tf32f(va[i].w);
                int rb = i * 8 + br;
                float* db = sB + rb * PADB + bc4;
                db[0] = tf32f(vb[i].x); db[1] = tf32f(vb[i].y);
                db[2] = tf32f(vb[i].z); db[3] = tf32f(vb[i].w);
            }
            __syncthreads();
            // prefetch next B chunk (DRAM latency overlaps compute)
            if (kc + 1 < NCH) {
                const float* bn = bp + (size_t)(k0 + KC) * ldb;
#pragma unroll
                for (int i = 0; i < 4; i++)
                    vb[i] = *(const float4*)(bn + (size_t)(i * 8) * ldb);
            }
            // compute
#pragma unroll
            for (int k8 = 0; k8 < KC; k8 += 8) {
                uint32_t af[4][4];
#pragma unroll
                for (int mt = 0; mt < 4; mt++) {
                    const float* ab = sA + (m0w + mt * 16 + r0) * PADA + k8 + kq;
                    af[mt][0] = __float_as_uint(ab[0]);
                    af[mt][1] = __float_as_uint(ab[8 * PADA]);
                    af[mt][2] = __float_as_uint(ab[4]);
                    af[mt][3] = __float_as_uint(ab[8 * PADA + 4]);
                }
#pragma unroll
                for (int nt = 0; nt < 4; nt++) {
                    const float* bb = sB + (k8 + kq) * PADB + n0w + nt * 8 + nq;
                    uint32_t bf[2] = { __float_as_uint(bb[0]), __float_as_uint(bb[4 * PADB]) };
#pragma unroll
                    for (int mt = 0; mt < 4; mt++)
                        mma_tf32(acc[mt][nt], af[mt], bf);
                }
            }
            __syncthreads();
        }
    }
};

#define GEMM_SMEM ((128 + A_FL + B_FL) * 4)   // rowtok + A + B (single buffer)

// ---------------- gate GEMM: g_raw = x[rowtok] @ Wg ----------------
__global__ __launch_bounds__(256, 2) void gate_tc(
    const float* __restrict__ x, const float* __restrict__ Wg) {
    extern __shared__ float sm[];
    const int e = blockIdx.z;
    const int ne = g_off[e + 1] - g_off[e];
    const int m0 = blockIdx.y * BMT;
    if (m0 >= ne) return;
    const int n0 = blockIdx.x * BNT;
    const int off = g_off[e];

    int* rowtok = (int*)sm;
    const int tid = threadIdx.x;
    const int wid = tid >> 5;
    const int lane = tid & 31;
    if (tid < BMT) {
        int m = m0 + tid;
        rowtok[tid] = g_list[off + (m < ne ? m : 0)];
    }
    __syncthreads();

    const float* aptr[4];
#pragma unroll
    for (int i = 0; i < 4; i++) {
        int r = i * 32 + (tid >> 3);
        aptr[i] = x + (size_t)rowtok[r] * HDIM + (tid & 7) * 4;
    }
    const float* bptr = Wg + (size_t)e * HDIM * IDIM + n0;

    float acc[4][4][4];
#pragma unroll
    for (int i = 0; i < 4; i++)
#pragma unroll
        for (int j = 0; j < 4; j++)
#pragma unroll
            for (int q = 0; q < 4; q++) acc[i][j][q] = 0.f;

    GemmCore::run(sm + 128, sm + 128 + A_FL, aptr, bptr, IDIM,
                  HDIM / KC, tid, wid, lane, acc);

    const int m0w = (wid >> 2) * 64;
    const int n0w = (wid & 3) * 32;
#pragma unroll
    for (int mt = 0; mt < 4; mt++) {
        int rloc = m0w + mt * 16 + (lane >> 2);
#pragma unroll
        for (int h = 0; h < 2; h++) {
            int m = m0 + rloc + h * 8;
            if (m < ne) {
                float* orow = g_raw + (size_t)(off + m) * IDIM + n0;
#pragma unroll
                for (int nt = 0; nt < 4; nt++) {
                    int c = n0w + nt * 8 + 2 * (lane & 3);
                    float2 v;
                    v.x = acc[mt][nt][2 * h];
                    v.y = acc[mt][nt][2 * h + 1];
                    *(float2*)(orow + c) = v;
                }
            }
        }
    }
}

// ---------------- up GEMM + SwiGLU: g_act = silu(g_raw) * (x @ Wu) ----------
__global__ __launch_bounds__(256, 2) void up_tc(
    const float* __restrict__ x, const float* __restrict__ Wu) {
    extern __shared__ float sm[];
    const int e = blockIdx.z;
    const int ne = g_off[e + 1] - g_off[e];
    const int m0 = blockIdx.y * BMT;
    if (m0 >= ne) return;
    const int n0 = blockIdx.x * BNT;
    const int off = g_off[e];

    int* rowtok = (int*)sm;
    const int tid = threadIdx.x;
    const int wid = tid >> 5;
    const int lane = tid & 31;
    if (tid < BMT) {
        int m = m0 + tid;
        rowtok[tid] = g_list[off + (m < ne ? m : 0)];
    }
    __syncthreads();

    const float* aptr[4];
#pragma unroll
    for (int i = 0; i < 4; i++) {
        int r = i * 32 + (tid >> 3);
        aptr[i] = x + (size_t)rowtok[r] * HDIM + (tid & 7) * 4;
    }
    const float* bptr = Wu + (size_t)e * HDIM * IDIM + n0;

    float acc[4][4][4];
#pragma unroll
    for (int i = 0; i < 4; i++)
#pragma unroll
        for (int j = 0; j < 4; j++)
#pragma unroll
            for (int q = 0; q < 4; q++) acc[i][j][q] = 0.f;

    GemmCore::run(sm + 128, sm + 128 + A_FL, aptr, bptr, IDIM,
                  HDIM / KC, tid, wid, lane, acc);

    const int m0w = (wid >> 2) * 64;
    const int n0w = (wid & 3) * 32;
#pragma unroll
    for (int mt = 0; mt < 4; mt++) {
        int rloc = m0w + mt * 16 + (lane >> 2);
#pragma unroll
        for (int h = 0; h < 2; h++) {
            int m = m0 + rloc + h * 8;
            if (m < ne) {
                const float* grow = g_raw + (size_t)(off + m) * IDIM + n0;
                float* orow = g_act + (size_t)(off + m) * IDIM + n0;
#pragma unroll
                for (int nt = 0; nt < 4; nt++) {
                    int c = n0w + nt * 8 + 2 * (lane & 3);
                    float2 gv = *(const float2*)(grow + c);
                    float2 v;
                    v.x = gv.x / (1.f + expf(-gv.x)) * acc[mt][nt][2 * h];
                    v.y = gv.y / (1.f + expf(-gv.y)) * acc[mt][nt][2 * h + 1];
                    *(float2*)(orow + c) = v;
                }
            }
        }
    }
}

// ---------------- down GEMM: g_pairout = wt * (g_act @ Wd) ----------------
__global__ __launch_bounds__(256, 2) void down_tc(const float* __restrict__ Wd) {
    extern __shared__ float sm[];
    const int e = blockIdx.z;
    const int ne = g_off[e + 1] - g_off[e];
    const int m0 = blockIdx.y * BMT;
    if (m0 >= ne) return;
    const int n0 = blockIdx.x * BNT;
    const int off = g_off[e];

    const int tid = threadIdx.x;
    const int wid = tid >> 5;
    const int lane = tid & 31;

    const float* aptr[4];
#pragma unroll
    for (int i = 0; i < 4; i++) {
        int r = i * 32 + (tid >> 3);
        int idx = off + m0 + r;
        if (idx >= NPAIR) idx = NPAIR - 1;
        aptr[i] = g_act + (size_t)idx * IDIM + (tid & 7) * 4;
    }
    const float* bptr = Wd + (size_t)e * IDIM * HDIM + n0;

    float acc[4][4][4];
#pragma unroll
    for (int i = 0; i < 4; i++)
#pragma unroll
        for (int j = 0; j < 4; j++)
#pragma unroll
            for (int q = 0; q < 4; q++) acc[i][j][q] = 0.f;

    GemmCore::run(sm + 128, sm + 128 + A_FL, aptr, bptr, HDIM,
                  IDIM / KC, tid, wid, lane, acc);

    const int m0w = (wid >> 2) * 64;
    const int n0w = (wid & 3) * 32;
#pragma unroll
    for (int mt = 0; mt < 4; mt++) {
        int rloc = m0w + mt * 16 + (lane >> 2);
#pragma unroll
        for (int h = 0; h < 2; h++) {
            int m = m0 + rloc + h * 8;
            if (m < ne) {
                float wt = g_wt[off + m];
                float* orow = g_pairout + (size_t)(off + m) * HDIM + n0;
#pragma unroll
                for (int nt = 0; nt < 4; nt++) {
                    int c = n0w + nt * 8 + 2 * (lane & 3);
                    float2 v;
                    v.x = wt * acc[mt][nt][2 * h];
                    v.y = wt * acc[mt][nt][2 * h + 1];
                    *(float2*)(orow + c) = v;
                }
            }
        }
    }
}

// out[t, :] = pairout[p0, :] + pairout[p1, :]
__global__ void combine_kernel(float* __restrict__ out) {
    int idx = blockIdx.x * blockDim.x + threadIdx.x;
    int t = idx >> 8;
    int h4 = idx & 255;
    int p0 = g_tokpair[t * 2 + 0];
    int p1 = g_tokpair[t * 2 + 1];
    const float4* po = (const float4*)g_pairout;
    float4 a = po[(size_t)p0 * 256 + h4];
    float4 b = po[(size_t)p1 * 256 + h4];
    float4 r;
    r.x = a.x + b.x; r.y = a.y + b.y; r.z = a.z + b.z; r.w = a.w + b.w;
    ((float4*)out)[idx] = r;
}

// ---------------- launch ----------------
extern "C" void kernel_launch(void* const* d_in, const int* in_sizes, int n_in,
                              void* d_out, int out_size) {
    const float* x  = (const float*)d_in[0];
    const float* gw = (const float*)d_in[1];
    const float* Wg = (const float*)d_in[2];
    const float* Wu = (const float*)d_in[3];
    const float* Wd = (const float*)d_in[4];
    float* out = (float*)d_out;
    float* out_logits = out + (size_t)T_TOK * HDIM;

    router_kernel<<<T_TOK, 128>>>(x, gw, out_logits);
    scan_kernel<<<1, 1>>>();
    assign_kernel<<<T_TOK / 256, 256>>>();
    gate_tc<<<dim3(IDIM / BNT, NPAIR / BMT, EDIM), 256, GEMM_SMEM>>>(x, Wg);
    up_tc<<<dim3(IDIM / BNT, NPAIR / BMT, EDIM), 256, GEMM_SMEM>>>(x, Wu);
    down_tc<<<dim3(HDIM / BNT, NPAIR / BMT, EDIM), 256, GEMM_SMEM>>>(Wd);
    combine_kernel<<<(T_TOK * HDIM / 4) / 256, 256>>>(out);
}